// round 10
// baseline (speedup 1.0000x reference)
#include <cuda_runtime.h>
#include <cuda_bf16.h>

// Problem constants
#define NUM_HEADS 8
#define NUM_G     50
#define NUM_ELEM  100
#define NB        (NUM_ELEM * NUM_ELEM)   // 10000 distinct (src,dst) pairs
#define E_MAX     1000000
#define NREP      4                       // counter replicas per bin
#define RCAP      64                      // slots per replica (4*64 = 256 per bin)
#define OVF_MAX   8192

// offsets = linspace(0, 12, 50) -> spacing 12/49 ; std = 12/50
#define RBF_DELTA (12.0 / 49.0)
// k = -0.5/std^2 * log2(e)  (so exp() becomes ex2.approx)
#define RBF_K     (-8.680555555555555 * 1.4426950408889634)
// arg(g) = K*d^2 + MSLOPE*g*d + CQUAD*g^2
#define MSLOPE    (-2.0 * RBF_K * RBF_DELTA)
#define CQUAD     (RBF_K * RBF_DELTA * RBF_DELTA)

// ---- f32x2 packed helpers (sm_100+ PTX) -----------------------------------
__device__ __forceinline__ unsigned long long pk2(float x, float y) {
    unsigned long long r;
    asm("mov.b64 %0, {%1, %2};" : "=l"(r) : "f"(x), "f"(y));
    return r;
}
__device__ __forceinline__ void upk2(unsigned long long v, float& x, float& y) {
    asm("mov.b64 {%0, %1}, %2;" : "=f"(x), "=f"(y) : "l"(v));
}
__device__ __forceinline__ unsigned long long add2(unsigned long long a, unsigned long long b) {
    unsigned long long d;
    asm("add.rn.f32x2 %0, %1, %2;" : "=l"(d) : "l"(a), "l"(b));
    return d;
}
__device__ __forceinline__ unsigned long long fma2(unsigned long long a, unsigned long long b,
                                                   unsigned long long c) {
    unsigned long long d;
    asm("fma.rn.f32x2 %0, %1, %2, %3;" : "=l"(d) : "l"(a), "l"(b), "l"(c));
    return d;
}
__device__ __forceinline__ float ex2(float x) {
    float r;
    asm("ex2.approx.f32 %0, %1;" : "=f"(r) : "f"(x));
    return r;
}

// Scratch (no allocations allowed) -------------------------------------------
// g_cnt4 starts zeroed (device global); k_compute re-zeros its bin each launch.
__device__ int4 g_cnt4[NB];          // 4 replica counters per bin
__device__ int2 g_bins[NB * NREP * RCAP];  // {edge_id, dist_bits} (20 MB)
__device__ int  g_ovf_cnt;
__device__ int  g_ovf[OVF_MAX];

// K1: key + replica rank + direct bucket store --------------------------------
__global__ __launch_bounds__(256) void k_key_direct(
    const int*   __restrict__ anum,
    const int*   __restrict__ esrc,
    const int*   __restrict__ edst,
    const float* __restrict__ dist,
    int E)
{
    const int S   = gridDim.x * blockDim.x;
    const int idx = blockIdx.x * blockDim.x + threadIdx.x;

#pragma unroll
    for (int u = 0; u < 2; u++) {
        int e = idx + u * S;
        if (e < E) {
            int k = __ldg(anum + __ldg(esrc + e)) * NUM_ELEM
                  + __ldg(anum + __ldg(edst + e));
            float d = __ldg(dist + e);
            int r = e & (NREP - 1);              // replica: spreads within a warp
            int pos = atomicAdd(&((int*)&g_cnt4[k])[r], 1);
            if (pos < RCAP) {
                g_bins[(k * NREP + r) * RCAP + pos] = make_int2(e, __float_as_int(d));
            } else {
                int o = atomicAdd(&g_ovf_cnt, 1);
                if (o < OVF_MAX) g_ovf[o] = e;
            }
        }
    }
}

// K2: one block per pair; walks the 4 replica chunks; 2 edges per thread -------
__global__ __launch_bounds__(64, 14) void k_compute(
    const float* __restrict__ emb,
    float*       __restrict__ out)
{
    int b = blockIdx.x;                          // pair key
    int4 c4 = g_cnt4[b];                         // all threads read BEFORE reset
    int c0 = min(c4.x, RCAP), c1 = min(c4.y, RCAP);
    int c2 = min(c4.z, RCAP), c3 = min(c4.w, RCAP);
    int s0 = c0, s1 = s0 + c1, s2 = s1 + c2;
    int cnt = s2 + c3;
    const int2* bin = &g_bins[b * (NREP * RCAP)];

    // Ws2[j][h] = { w[h][2j], w[h][2j+1] } : 25 x 8 u64 = 1600 B
    __shared__ __align__(16) unsigned long long Ws2[25 * 8];
    if (cnt > 0) {
        const unsigned long long* W64 =
            (const unsigned long long*)(emb + (size_t)b * (NUM_HEADS * NUM_G));
        for (int i = threadIdx.x; i < 25 * NUM_HEADS; i += 64) {
            int h = i / 25, j = i % 25;          // source u64 index = h*25+j (coalesced)
            Ws2[j * 8 + h] = __ldg(W64 + i);
        }
    }
    __syncthreads();
    if (threadIdx.x == 0) g_cnt4[b] = make_int4(0, 0, 0, 0);  // next launch/replay
    if (cnt == 0) return;

    for (int base = 0; base < cnt; base += 128) {
        int i0 = base + threadIdx.x;
        int i1 = i0 + 64;
        if (i0 >= cnt) break;                    // i1 active => i0 active
        bool has1 = (i1 < cnt);

        // map logical index -> replica chunk slot
        int a0 = (i0 < s0) ? i0
               : (i0 < s1) ? (RCAP     + i0 - s0)
               : (i0 < s2) ? (2 * RCAP + i0 - s1)
               :             (3 * RCAP + i0 - s2);
        int j1 = has1 ? i1 : i0;
        int a1 = (j1 < s0) ? j1
               : (j1 < s1) ? (RCAP     + j1 - s0)
               : (j1 < s2) ? (2 * RCAP + j1 - s1)
               :             (3 * RCAP + j1 - s2);

        int2  pe0 = __ldg(&bin[a0]);
        int2  pe1 = __ldg(&bin[a1]);
        float dA  = __int_as_float(pe0.y);
        float dB  = __int_as_float(pe1.y);

        const unsigned long long dA2 = pk2(dA, dA);
        const unsigned long long dB2 = pk2(dB, dB);
        const float tA = (float)RBF_K * dA * dA;
        const float tB = (float)RBF_K * dB * dB;
        const unsigned long long tA2 = pk2(tA, tA);
        const unsigned long long tB2 = pk2(tB, tB);

        unsigned long long accA[NUM_HEADS], accB[NUM_HEADS];
#pragma unroll
        for (int h = 0; h < NUM_HEADS; h++) { accA[h] = 0ull; accB[h] = 0ull; }

#pragma unroll
        for (int j = 0; j < NUM_G / 2; j++) {
            const float g0 = (float)(2 * j), g1 = (float)(2 * j + 1);
            unsigned long long m2 = pk2((float)(MSLOPE * g0), (float)(MSLOPE * g1));
            unsigned long long q2 = pk2((float)(CQUAD * g0 * g0), (float)(CQUAD * g1 * g1));

            unsigned long long argA = fma2(m2, dA2, add2(tA2, q2));
            unsigned long long argB = fma2(m2, dB2, add2(tB2, q2));
            float a0f, a1f, b0f, b1f;
            upk2(argA, a0f, a1f);
            upk2(argB, b0f, b1f);
            unsigned long long rA = pk2(ex2(a0f), ex2(a1f));
            unsigned long long rB = pk2(ex2(b0f), ex2(b1f));

            const ulonglong2* wrow = (const ulonglong2*)&Ws2[j * 8];
            ulonglong2 w01 = wrow[0];
            ulonglong2 w23 = wrow[1];
            ulonglong2 w45 = wrow[2];
            ulonglong2 w67 = wrow[3];
            accA[0] = fma2(w01.x, rA, accA[0]);  accB[0] = fma2(w01.x, rB, accB[0]);
            accA[1] = fma2(w01.y, rA, accA[1]);  accB[1] = fma2(w01.y, rB, accB[1]);
            accA[2] = fma2(w23.x, rA, accA[2]);  accB[2] = fma2(w23.x, rB, accB[2]);
            accA[3] = fma2(w23.y, rA, accA[3]);  accB[3] = fma2(w23.y, rB, accB[3]);
            accA[4] = fma2(w45.x, rA, accA[4]);  accB[4] = fma2(w45.x, rB, accB[4]);
            accA[5] = fma2(w45.y, rA, accA[5]);  accB[5] = fma2(w45.y, rB, accB[5]);
            accA[6] = fma2(w67.x, rA, accA[6]);  accB[6] = fma2(w67.x, rB, accB[6]);
            accA[7] = fma2(w67.y, rA, accA[7]);  accB[7] = fma2(w67.y, rB, accB[7]);
        }

        {
            float r[NUM_HEADS];
#pragma unroll
            for (int h = 0; h < NUM_HEADS; h++) {
                float x0, x1;
                upk2(accA[h], x0, x1);
                r[h] = x0 + x1;
            }
            float4* o = (float4*)(out + (size_t)pe0.x * NUM_HEADS);
            o[0] = make_float4(r[0], r[1], r[2], r[3]);
            o[1] = make_float4(r[4], r[5], r[6], r[7]);
        }
        if (has1) {
            float r[NUM_HEADS];
#pragma unroll
            for (int h = 0; h < NUM_HEADS; h++) {
                float x0, x1;
                upk2(accB[h], x0, x1);
                r[h] = x0 + x1;
            }
            float4* o = (float4*)(out + (size_t)pe1.x * NUM_HEADS);
            o[0] = make_float4(r[0], r[1], r[2], r[3]);
            o[1] = make_float4(r[4], r[5], r[6], r[7]);
        }
    }
}

// K3: overflow cleanup (expected count 0); single block so the counter reset
// is safely ordered after all processing.
__global__ __launch_bounds__(256) void k_ovf(
    const int*   __restrict__ anum,
    const int*   __restrict__ esrc,
    const int*   __restrict__ edst,
    const float* __restrict__ dist,
    const float* __restrict__ emb,
    float*       __restrict__ out)
{
    int n = g_ovf_cnt;
    if (n > OVF_MAX) n = OVF_MAX;
    for (int i = threadIdx.x; i < n; i += 256) {
        int e = g_ovf[i];
        int k = __ldg(anum + __ldg(esrc + e)) * NUM_ELEM
              + __ldg(anum + __ldg(edst + e));
        float d = __ldg(dist + e);
        const float* W = emb + (size_t)k * (NUM_HEADS * NUM_G);
        float t = (float)RBF_K * d * d;
        float rbf[NUM_G];
#pragma unroll
        for (int g = 0; g < NUM_G; g++)
            rbf[g] = ex2(t + (float)(MSLOPE * g) * d + (float)(CQUAD * g * g));
        for (int h = 0; h < NUM_HEADS; h++) {
            float a = 0.f;
#pragma unroll
            for (int g = 0; g < NUM_G; g++)
                a = fmaf(__ldg(W + h * NUM_G + g), rbf[g], a);
            out[(size_t)e * NUM_HEADS + h] = a;
        }
    }
    __syncthreads();
    if (threadIdx.x == 0) g_ovf_cnt = 0;        // reset for next launch/replay
}

extern "C" void kernel_launch(void* const* d_in, const int* in_sizes, int n_in,
                              void* d_out, int out_size)
{
    const int*   anum = (const int*)d_in[0];
    const int*   eidx = (const int*)d_in[1];   // [2, E]
    const float* dist = (const float*)d_in[2];
    const float* emb  = (const float*)d_in[3];
    float*       out  = (float*)d_out;

    int E = in_sizes[2];                       // dist has E elements
    if (E > E_MAX) E = E_MAX;

    k_key_direct<<<2048, 256>>>(anum, eidx, eidx + E, dist, E);
    k_compute<<<NB, 64>>>(emb, out);
    k_ovf<<<1, 256>>>(anum, eidx, eidx + E, dist, emb, out);
}